// round 17
// baseline (speedup 1.0000x reference)
#include <cuda_runtime.h>
#include <cuda_bf16.h>
#include <math.h>
#include <stdint.h>

constexpr int kD = 2048, kE = 32, kK = 8, kI = 1024, kMaxT = 8192;
constexpr int kMaxRows = kMaxT * kK;   // 65536

// ---------------- scratch (1.02 GB total — within R14-proven envelope) ----------------
__device__ int   g_topi[kMaxRows];
__device__ float g_topw[kMaxRows];
__device__ int   g_rowtok[kMaxRows];
__device__ float g_rowscale[kMaxRows];
__device__ int   g_counts[kE];
__device__ int   g_offsets[kE + 1];
__device__ int   g_cursor[kE];
__device__ float g_sumprob[kE];
__device__ int   g_flag;
// pre-split transposed weights: [e][n][k] bf16, k contiguous
__device__ __align__(16) __nv_bfloat16 g_WgThi[(size_t)kE * kI * kD];
__device__ __align__(16) __nv_bfloat16 g_WgTlo[(size_t)kE * kI * kD];
__device__ __align__(16) __nv_bfloat16 g_WuThi[(size_t)kE * kI * kD];
__device__ __align__(16) __nv_bfloat16 g_WuTlo[(size_t)kE * kI * kD];
__device__ __align__(16) __nv_bfloat16 g_WdThi[(size_t)kE * kD * kI];
__device__ __align__(16) __nv_bfloat16 g_WdTlo[(size_t)kE * kD * kI];
// H (gemm1 output) pre-split bf16
__device__ __align__(16) __nv_bfloat16 g_Hhi[(size_t)kMaxRows * kI];
__device__ __align__(16) __nv_bfloat16 g_Hlo[(size_t)kMaxRows * kI];

// ---------------- helpers ----------------
__device__ __forceinline__ uint32_t smem_u32(const void* p) {
    uint32_t a;
    asm("{ .reg .u64 t; cvta.to.shared.u64 t, %1; cvt.u32.u64 %0, t; }" : "=r"(a) : "l"(p));
    return a;
}
__device__ __forceinline__ void mma_bf16(float* c, const uint32_t* a, const uint32_t* b) {
    asm volatile(
        "mma.sync.aligned.m16n8k16.row.col.f32.bf16.bf16.f32 "
        "{%0,%1,%2,%3}, {%4,%5,%6,%7}, {%8,%9}, {%0,%1,%2,%3};"
        : "+f"(c[0]), "+f"(c[1]), "+f"(c[2]), "+f"(c[3])
        : "r"(a[0]), "r"(a[1]), "r"(a[2]), "r"(a[3]), "r"(b[0]), "r"(b[1]));
}
__device__ __forceinline__ void ldsm4(uint32_t* r, uint32_t addr) {
    asm volatile("ldmatrix.sync.aligned.m8n8.x4.shared.b16 {%0,%1,%2,%3}, [%4];"
                 : "=r"(r[0]), "=r"(r[1]), "=r"(r[2]), "=r"(r[3]) : "r"(addr));
}
// Truncation-based hi/lo split of a float pair, packed as bf16x2.
__device__ __forceinline__ void pack2(float a, float b, uint32_t& hi, uint32_t& lo) {
    uint32_t ra = __float_as_uint(a), rb = __float_as_uint(b);
    asm("prmt.b32 %0, %1, %2, 0x7632;" : "=r"(hi) : "r"(ra), "r"(rb));
    float la = a - __uint_as_float(ra & 0xFFFF0000u);
    float lb = b - __uint_as_float(rb & 0xFFFF0000u);
    asm("prmt.b32 %0, %1, %2, 0x7632;" : "=r"(lo) : "r"(__float_as_uint(la)), "r"(__float_as_uint(lb)));
}
__device__ __forceinline__ void trunc_split(float v, __nv_bfloat16& h, __nv_bfloat16& l) {
    uint32_t b = __float_as_uint(v);
    h = __ushort_as_bfloat16((unsigned short)(b >> 16));
    float lo = v - __uint_as_float(b & 0xFFFF0000u);
    l = __ushort_as_bfloat16((unsigned short)(__float_as_uint(lo) >> 16));
}

// ---------------- launch 1: transpose + split all three weight sets ----------------
// blockIdx.z: [0,32) Wg, [32,64) Wu, [64,96) Wd. Grid (32, 64, 96), all blocks active.
__global__ void tsplit_kernel(const float* __restrict__ Wg,
                              const float* __restrict__ Wu,
                              const float* __restrict__ Wd) {
    __shared__ float s[32][33];
    const int mat = blockIdx.z >> 5;
    const int e = blockIdx.z & 31;
    int R, C, r0, c0;
    const float* W;
    __nv_bfloat16 *Th, *Tl;
    if (mat < 2) {
        R = kD; C = kI;
        c0 = blockIdx.x * 32;            // over kI (32 blocks)
        r0 = blockIdx.y * 32;            // over kD (64 blocks)
        W  = (mat ? Wu : Wg) + (size_t)e * kD * kI;
        Th = (mat ? g_WuThi : g_WgThi) + (size_t)e * kI * kD;
        Tl = (mat ? g_WuTlo : g_WgTlo) + (size_t)e * kI * kD;
    } else {
        R = kI; C = kD;
        r0 = blockIdx.x * 32;            // over kI (32 blocks)
        c0 = blockIdx.y * 32;            // over kD (64 blocks)
        W  = Wd + (size_t)e * kI * kD;
        Th = g_WdThi + (size_t)e * kD * kI;
        Tl = g_WdTlo + (size_t)e * kD * kI;
    }
#pragma unroll
    for (int i = 0; i < 4; ++i)
        s[threadIdx.y + i * 8][threadIdx.x] =
            W[(size_t)(r0 + threadIdx.y + i * 8) * C + c0 + threadIdx.x];
    __syncthreads();
#pragma unroll
    for (int i = 0; i < 4; ++i) {
        float v = s[threadIdx.x][threadIdx.y + i * 8];
        size_t o = (size_t)(c0 + threadIdx.y + i * 8) * R + r0 + threadIdx.x;
        __nv_bfloat16 h, l;
        trunc_split(v, h, l);
        Th[o] = h;
        Tl[o] = l;
    }
}

// ---------------- launch 2: zero out + reset bookkeeping ----------------
__global__ void zeroreset_kernel(float* __restrict__ out, size_t n) {
    size_t i = (size_t)blockIdx.x * blockDim.x + threadIdx.x;
    size_t stride = (size_t)gridDim.x * blockDim.x;
    for (; i < n; i += stride) out[i] = 0.f;
    if (blockIdx.x == 0) {
        if (threadIdx.x < kE) {
            g_counts[threadIdx.x] = 0;
            g_cursor[threadIdx.x] = 0;
            g_sumprob[threadIdx.x] = 0.f;
        }
        if (threadIdx.x == 0) g_flag = 0;
    }
}

// ---------------- launch 3: router ----------------
__global__ void router_kernel(const float* __restrict__ x,
                              const float* __restrict__ Wgate, int T) {
    int warp = (blockIdx.x * blockDim.x + threadIdx.x) >> 5;
    int lane = threadIdx.x & 31;
    if (warp >= T) return;
    const float* xt = x + (size_t)warp * kD;

    float acc = 0.f;
#pragma unroll 4
    for (int d = 0; d < kD; ++d) acc += xt[d] * Wgate[d * kE + lane];

    float m = acc;
#pragma unroll
    for (int o = 16; o; o >>= 1) m = fmaxf(m, __shfl_xor_sync(0xffffffffu, m, o));
    float p = __expf(acc - m);
    float s = p;
#pragma unroll
    for (int o = 16; o; o >>= 1) s += __shfl_xor_sync(0xffffffffu, s, o);
    atomicAdd(&g_sumprob[lane], p / s);

    float v = acc;
    float topv[kK]; int topi[kK];
#pragma unroll
    for (int k = 0; k < kK; ++k) {
        float bv = v; int bi = lane;
#pragma unroll
        for (int o = 16; o; o >>= 1) {
            float ov = __shfl_xor_sync(0xffffffffu, bv, o);
            int   oi = __shfl_xor_sync(0xffffffffu, bi, o);
            if (ov > bv || (ov == bv && oi < bi)) { bv = ov; bi = oi; }
        }
        topv[k] = bv; topi[k] = bi;
        if (lane == bi) v = -INFINITY;
    }

    float mx = topv[0];
    float w[kK]; float se = 0.f;
#pragma unroll
    for (int k = 0; k < kK; ++k) { w[k] = __expf(topv[k] - mx); se += w[k]; }
#pragma unroll
    for (int k = 0; k < kK; ++k) {
        if (lane == k) {
            g_topi[warp * kK + k] = topi[k];
            g_topw[warp * kK + k] = w[k] / se;
            atomicAdd(&g_counts[topi[k]], 1);
        }
    }
}

// ---------------- launch 4: offsets + aux (block0) then scatter (spin-gated) ----------------
__global__ void osa_kernel(float* __restrict__ out, int T, int out_size) {
    if (blockIdx.x == 0 && threadIdx.x == 0) {
        int s = 0;
        for (int e = 0; e < kE; ++e) { g_offsets[e] = s; s += g_counts[e]; }
        g_offsets[kE] = s;
        if ((size_t)out_size > (size_t)T * kD) {
            float a = 0.f;
            for (int e = 0; e < kE; ++e) a += g_sumprob[e] * (float)g_counts[e];
            out[(size_t)T * kD] = a / ((float)T * (float)T);
        }
        __threadfence();
        atomicExch(&g_flag, 1);
    } else {
        while (atomicAdd(&g_flag, 0) == 0) {}
    }
    __syncthreads();
    int idx = blockIdx.x * blockDim.x + threadIdx.x;
    if (idx < T * kK) {
        int e = g_topi[idx];
        int pos = g_offsets[e] + atomicAdd(&g_cursor[e], 1);
        g_rowtok[pos]   = idx / kK;
        g_rowscale[pos] = g_topw[idx];
    }
}

// =========================================================================
// GEMM1 (launch 5): 128(M) x 64(N), BK=16, 256 threads, 2 CTAs/SM, fused gate+up.
// Double-buffered, one sync/stage, ldmatrix.x4. B from pre-split uint4 (no pack).
//   stage = 24576 B: AH@0(6144) AL@6144 GH@12288(3072) GL@15360 UH@18432 UL@21504
// =========================================================================
constexpr int G1_STG = 24576;
__global__ __launch_bounds__(256, 2) void gemm1_mma(const float* __restrict__ x) {
    extern __shared__ __align__(16) char sm[];
    __shared__ int   toks[128];
    __shared__ float scls[128];
    const int e = blockIdx.z;
    const int base  = g_offsets[e];
    const int count = g_offsets[e + 1] - base;
    const int m0 = blockIdx.y * 128;
    if (m0 >= count) return;
    const int n0 = blockIdx.x * 64;
    const int tid = threadIdx.x, lane = tid & 31, wid = tid >> 5;
    const int wm = wid & 3, wn = wid >> 2, g = lane >> 2, q = lane & 3;
    const uint32_t sb = smem_u32(sm);

    if (tid < 128) {
        int r = m0 + tid;
        toks[tid] = g_rowtok[base + ((r < count) ? r : (count - 1))];
        scls[tid] = (r < count) ? g_rowscale[base + r] : 0.f;
    }
    __syncthreads();

    const uint32_t aoff = (uint32_t)((wm * 32 + (lane & 7) + ((lane >> 3) & 1) * 8) * 48
                                     + ((lane >> 4) & 1) * 16);
    const uint32_t boff = (uint32_t)((wn * 32 + (lane & 7) + ((lane >> 4) & 1) * 8) * 48
                                     + ((lane >> 3) & 1) * 16);

    const int arow = tid >> 1, ah8 = (tid & 1) * 8;       // A: 128 rows, 8-k halves
    const int bn = tid & 63, kb = (tid >> 6) & 1;         // B: 64 n, 2 k-halves
    const int bmat = tid >> 7;                             // 0 = gate, 1 = up
    const __nv_bfloat16* bsrcH = (bmat ? g_WuThi : g_WgThi) + ((size_t)e * kI + n0 + bn) * kD + kb * 8;
    const __nv_bfloat16* bsrcL = (bmat ? g_WuTlo : g_WgTlo) + ((size_t)e * kI + n0 + bn) * kD + kb * 8;
    const float* asrc = x + (size_t)toks[arow] * kD + ah8;

    float4 ra0, ra1;
    uint4 rbh, rbl;

    auto load = [&](int s) {
        const int k0 = s * 16;
        ra0 = *(const float4*)(asrc + k0);
        ra1 = *(const float4*)(asrc + k0 + 4);
        rbh = *(const uint4*)(bsrcH + k0);
        rbl = *(const uint4*)(bsrcL + k0);
    };
    auto store = [&](int buf) {
        char* bb = sm + buf * G1_STG;
        uint32_t h0, l0, h1, l1, h2, l2, h3, l3;
        pack2(ra0.x, ra0.y, h0, l0);
        pack2(ra0.z, ra0.w, h1, l1);
        pack2(ra1.x, ra1.y, h2, l2);
        pack2(ra1.z, ra1.w, h3, l3);
        uint32_t o = (uint32_t)(arow * 48 + ah8 * 2);
        *(uint4*)(bb + o)        = make_uint4(h0, h1, h2, h3);
        *(uint4*)(bb + 6144 + o) = make_uint4(l0, l1, l2, l3);
        uint32_t bofs = 12288 + (uint32_t)bmat * 6144 + (uint32_t)(bn * 48 + kb * 16);
        *(uint4*)(bb + bofs)        = rbh;
        *(uint4*)(bb + bofs + 3072) = rbl;
    };

    float cg[2][4][4] = {}, cu[2][4][4] = {};
    load(0); store(0);
    __syncthreads();

    const int S = kD / 16;   // 128
    int buf = 0;
    for (int s = 0; s < S; ++s) {
        if (s + 1 < S) load(s + 1);
        const uint32_t bbu = sb + buf * G1_STG;
        uint32_t ah[2][4], al[2][4];
#pragma unroll
        for (int mt = 0; mt < 2; ++mt) {
            ldsm4(ah[mt], bbu + aoff + mt * 768);
            ldsm4(al[mt], bbu + 6144 + aoff + mt * 768);
        }
#pragma unroll
        for (int jp = 0; jp < 2; ++jp) {
            uint32_t gh[4], gl[4], uh[4], ul[4];
            ldsm4(gh, bbu + 12288 + boff + jp * 768);
            ldsm4(gl, bbu + 15360 + boff + jp * 768);
            ldsm4(uh, bbu + 18432 + boff + jp * 768);
            ldsm4(ul, bbu + 21504 + boff + jp * 768);
#pragma unroll
            for (int mt = 0; mt < 2; ++mt) {
                mma_bf16(cg[mt][jp * 2],     ah[mt], &gh[0]);
                mma_bf16(cg[mt][jp * 2],     ah[mt], &gl[0]);
                mma_bf16(cg[mt][jp * 2],     al[mt], &gh[0]);
                mma_bf16(cg[mt][jp * 2 + 1], ah[mt], &gh[2]);
                mma_bf16(cg[mt][jp * 2 + 1], ah[mt], &gl[2]);
                mma_bf16(cg[mt][jp * 2 + 1], al[mt], &gh[2]);
                mma_bf16(cu[mt][jp * 2],     ah[mt], &uh[0]);
                mma_bf16(cu[mt][jp * 2],     ah[mt], &ul[0]);
                mma_bf16(cu[mt][jp * 2],     al[mt], &uh[0]);
                mma_bf16(cu[mt][jp * 2 + 1], ah[mt], &uh[2]);
                mma_bf16(cu[mt][jp * 2 + 1], ah[mt], &ul[2]);
                mma_bf16(cu[mt][jp * 2 + 1], al[mt], &uh[2]);
            }
        }
        if (s + 1 < S) store(buf ^ 1);
        __syncthreads();
        buf ^= 1;
    }

    // epilogue: H = silu(gate) * up * scale, written as pre-split bf16 hi/lo
#pragma unroll
    for (int mt = 0; mt < 2; ++mt)
#pragma unroll
        for (int h = 0; h < 2; ++h) {
            int rl = wm * 32 + mt * 16 + g + h * 8;
            if (m0 + rl < count) {
                float sc = scls[rl];
                size_t off = (size_t)(base + m0 + rl) * kI + n0 + wn * 32 + q * 2;
#pragma unroll
                for (int j = 0; j < 4; ++j) {
                    float g0 = cg[mt][j][2 * h], g1 = cg[mt][j][2 * h + 1];
                    float u0 = cu[mt][j][2 * h], u1 = cu[mt][j][2 * h + 1];
                    float h0 = g0 / (1.f + __expf(-g0)) * u0 * sc;
                    float h1 = g1 / (1.f + __expf(-g1)) * u1 * sc;
                    uint32_t phi, plo;
                    pack2(h0, h1, phi, plo);
                    *(uint32_t*)(g_Hhi + off + j * 8) = phi;
                    *(uint32_t*)(g_Hlo + off + j * 8) = plo;
                }
            }
        }
}

// =========================================================================
// GEMM2 (launch 6): 128(M) x 128(N), BK=16, 256 threads, 2 CTAs/SM.
// Double-buffered, one sync/stage, ldmatrix.x4. A & B pre-split uint4 (no pack).
//   stage = 24576 B: AH@0 AL@6144 BH@12288 BL@18432. atomicAdd epilogue.
// =========================================================================
constexpr int G2_STG = 24576;
__global__ __launch_bounds__(256, 2) void gemm2_mma(float* __restrict__ out) {
    extern __shared__ __align__(16) char sm[];
    __shared__ int toks[128];
    const int e = blockIdx.z;
    const int base  = g_offsets[e];
    const int count = g_offsets[e + 1] - base;
    const int m0 = blockIdx.y * 128;
    if (m0 >= count) return;
    const int n0 = blockIdx.x * 128;
    const int tid = threadIdx.x, lane = tid & 31, wid = tid >> 5;
    const int wm = wid & 3, wn = wid >> 2, g = lane >> 2, q = lane & 3;
    const uint32_t sb = smem_u32(sm);

    if (tid < 128) {
        int r = m0 + tid;
        toks[tid] = g_rowtok[base + ((r < count) ? r : (count - 1))];
    }
    __syncthreads();

    const uint32_t aoff = (uint32_t)((wm * 32 + (lane & 7) + ((lane >> 3) & 1) * 8) * 48
                                     + ((lane >> 4) & 1) * 16);
    const uint32_t boff = (uint32_t)((wn * 64 + (lane & 7) + ((lane >> 4) & 1) * 8) * 48
                                     + ((lane >> 3) & 1) * 16);

    const int arow = tid >> 1, ah8 = (tid & 1) * 8;
    const int bn = tid & 127, bk8 = (tid >> 7) * 8;
    const int arl = (m0 + arow < count) ? (m0 + arow) : (count - 1);
    const __nv_bfloat16* asrcH = g_Hhi + (size_t)(base + arl) * kI + ah8;
    const __nv_bfloat16* asrcL = g_Hlo + (size_t)(base + arl) * kI + ah8;
    const __nv_bfloat16* bsrcH = g_WdThi + ((size_t)e * kD + n0 + bn) * kI + bk8;
    const __nv_bfloat16* bsrcL = g_WdTlo + ((size_t)e * kD + n0 + bn) * kI + bk8;

    uint4 rah, ral, rbh, rbl;

    auto load = [&](int s) {
        const int k0 = s * 16;
        rah = *(const uint4*)(asrcH + k0);
        ral = *(const uint4*)(asrcL + k0);
        rbh = *(const uint4*)(bsrcH + k0);
        rbl = *(const uint4*)(bsrcL + k0);
    };
    auto store = [&](int buf) {
        char* bb = sm + buf * G2_STG;
        uint32_t oA = (uint32_t)(arow * 48 + ah8 * 2);
        *(uint4*)(bb + oA)        = rah;
        *(uint4*)(bb + 6144 + oA) = ral;
        uint32_t oB = (uint32_t)(12288 + bn * 48 + bk8 * 2);
        *(uint4*)(bb + oB)        = rbh;
        *(uint4*)(bb + 6144 + oB) = rbl;
    };

    float c[2][8][4] = {};
    load(0); store(0);
    __syncthreads();

    const int S = kI / 16;   // 64
    int buf = 0;
    for (int s = 0; s < S; ++s) {
        if (s + 1 < S) load(s + 1);
        const uint32_t bbu = sb + buf * G2_STG;
        uint32_t ah[2][4], al[2][4];
#pragma unroll
        for (int mt = 0; mt < 2; ++mt) {
            ldsm4(ah[mt], bbu + aoff + mt * 768);
            ldsm4(al[mt], bbu + 6144 + aoff + mt * 768);
        }
#pragma unroll
        for (int jp = 0; jp < 4; ++jp) {
            uint32_t bh[4], bl[4];
            ldsm4(bh, bbu + 12288 + boff + jp * 768);
            ldsm4(bl, bbu + 18432 + boff + jp * 768);
#pragma unroll
            for (int mt = 0; mt < 2; ++mt) {
                mma_bf16(c[mt][jp * 2],     ah[mt], &bh[0]);
                mma_bf16(c[mt][jp * 2],     ah[mt], &bl[0]);
                mma_bf16(c[mt][jp * 2],     al[mt], &bh[0]);
                mma_bf16(c[mt][jp * 2 + 1], ah[mt], &bh[2]);
                mma_bf16(c[mt][jp * 2 + 1], ah[mt], &bl[2]);
                mma_bf16(c[mt][jp * 2 + 1], al[mt], &bh[2]);
            }
        }
        if (s + 1 < S) store(buf ^ 1);
        __syncthreads();
        buf ^= 1;
    }

#pragma unroll
    for (int mt = 0; mt < 2; ++mt)
#pragma unroll
        for (int h = 0; h < 2; ++h) {
            int rl = wm * 32 + mt * 16 + g + h * 8;
            if (m0 + rl < count) {
                int tok = toks[rl];
                float* op = out + (size_t)tok * kD + n0 + wn * 64 + q * 2;
#pragma unroll
                for (int j = 0; j < 8; ++j) {
                    atomicAdd(&op[j * 8],     c[mt][j][2 * h]);
                    atomicAdd(&op[j * 8 + 1], c[mt][j][2 * h + 1]);
                }
            }
        }
}

// ---------------- launch ----------------
extern "C" void kernel_launch(void* const* d_in, const int* in_sizes, int n_in,
                              void* d_out, int out_size) {
    const float* x     = (const float*)d_in[0];
    const float* Wgate = (const float*)d_in[1];
    const float* Wg    = (const float*)d_in[2];
    const float* Wu    = (const float*)d_in[3];
    const float* Wd    = (const float*)d_in[4];
    float* out = (float*)d_out;

    const int T = in_sizes[0] / kD;

    cudaFuncSetAttribute(gemm1_mma, cudaFuncAttributeMaxDynamicSharedMemorySize, 2 * G1_STG);
    cudaFuncSetAttribute(gemm2_mma, cudaFuncAttributeMaxDynamicSharedMemorySize, 2 * G2_STG);

    tsplit_kernel<<<dim3(32, 64, 3 * kE), dim3(32, 8)>>>(Wg, Wu, Wd);      // launch 1
    zeroreset_kernel<<<2048, 256>>>(out, (size_t)out_size);                 // launch 2
    router_kernel<<<(T + 7) / 8, 256>>>(x, Wgate, T);                       // launch 3
    osa_kernel<<<(T * kK + 255) / 256, 256>>>(out, T, out_size);            // launch 4
    gemm1_mma<<<dim3(kI / 64, kMaxT / 128, kE), 256, 2 * G1_STG>>>(x);      // launch 5
    gemm2_mma<<<dim3(kD / 128, kMaxT / 128, kE), 256, 2 * G2_STG>>>(out);   // launch 6
}